// round 13
// baseline (speedup 1.0000x reference)
#include <cuda_runtime.h>
#include <cuda_fp16.h>

#define NN   100000
#define EE   20000
#define NNZV 1000000
#define DIM  128

#define NBE 20    // edge scan blocks
#define NBN 98    // node scan blocks

struct alignas(8) h4 { __half2 a, b; };

// ---- scratch: ~58 MB device globals ----
// INVARIANT: g_ecnt/g_ncnt are zero at kernel_launch entry. Static zero-init
// covers the first call; scanBC_kernel re-zeroes them after use every call.
__device__ int    g_ecnt[EE];
__device__ int    g_ncnt[NN];
__device__ int    g_eoff[EE + 1];
__device__ int    g_noff[NN + 1];
__device__ int    g_erank[NNZV];      // rank of entry within its edge bucket (4 MB)
__device__ int    g_nrank[NNZV];      // rank of entry within its node bucket (4 MB)
__device__ int    g_pe[64];
__device__ int    g_pn[128];
__device__ int    g_erows[NNZV];      // CSR by edge: node idx per slot (4 MB)
__device__ int    g_ncols[NNZV];      // CSC by node: edge idx per slot (4 MB)
__device__ __half g_xh[NN * DIM];     // 25.6 MB  fp16(dv^-1/2 * X)
__device__ float  g_m[EE * DIM];      // 10.24 MB fp32 hyperedge features
__device__ __half g_m2h[EE * DIM];    // 5.12 MB  fp16 (m @ W)
__device__ float  g_dvis[NN];         // dv^-1/2
__device__ float  g_deinv[EE];        // de^-1

// ---- 1) prep: scales + histogram-with-rank + X->fp16 ----
__global__ void prep_kernel(const float* __restrict__ X,
                            const float* __restrict__ dv,
                            const float* __restrict__ de,
                            const int*   __restrict__ rows,
                            const int*   __restrict__ cols) {
    int tid = blockIdx.x * blockDim.x + threadIdx.x;
    int stride = gridDim.x * blockDim.x;

    for (int i = tid; i < NN; i += stride) g_dvis[i] = rsqrtf(__ldg(dv + i));
    for (int i = tid; i < EE; i += stride) g_deinv[i] = 1.0f / __ldg(de + i);

    // degree histogram; the atomic's return value IS the entry's bucket rank
    const int4* rows4 = reinterpret_cast<const int4*>(rows);
    const int4* cols4 = reinterpret_cast<const int4*>(cols);
    int4* erank4 = reinterpret_cast<int4*>(g_erank);
    int4* nrank4 = reinterpret_cast<int4*>(g_nrank);
    for (int u = tid; u < NNZV / 4; u += stride) {
        int4 c = __ldg(cols4 + u);
        int4 r = __ldg(rows4 + u);
        int4 er, nr;
        er.x = atomicAdd(&g_ecnt[c.x], 1); er.y = atomicAdd(&g_ecnt[c.y], 1);
        er.z = atomicAdd(&g_ecnt[c.z], 1); er.w = atomicAdd(&g_ecnt[c.w], 1);
        nr.x = atomicAdd(&g_ncnt[r.x], 1); nr.y = atomicAdd(&g_ncnt[r.y], 1);
        nr.z = atomicAdd(&g_ncnt[r.z], 1); nr.w = atomicAdd(&g_ncnt[r.w], 1);
        erank4[u] = er;
        nrank4[u] = nr;
    }

    // X -> fp16 with dv^-1/2 folded (HBM-stream-bound; overlaps atomics above)
    const float4* X4 = reinterpret_cast<const float4*>(X);
    h4* Xh = reinterpret_cast<h4*>(g_xh);
    const int UNITS = NN * (DIM / 4);
    for (int u = tid; u < UNITS; u += stride) {
        int r = u >> 5;
        float s = rsqrtf(__ldg(dv + r));
        float4 x = __ldg(X4 + u);
        h4 o;
        o.a = __floats2half2_rn(s * x.x, s * x.y);
        o.b = __floats2half2_rn(s * x.z, s * x.w);
        Xh[u] = o;
    }
}

// ---- 2) scanA: per-1024-block exclusive scan, fused edges+nodes ----
__device__ __forceinline__ void block_scan_body(const int* cnt, int* off,
                                                int* partial, int len, int blk) {
    __shared__ int ws[32];
    int tid = threadIdx.x;
    int lane = tid & 31, wid = tid >> 5;
    int i = blk * 1024 + tid;
    int v = (i < len) ? cnt[i] : 0;
    int sum = v;
#pragma unroll
    for (int d = 1; d < 32; d <<= 1) {
        int t = __shfl_up_sync(0xffffffffu, sum, d);
        if (lane >= d) sum += t;
    }
    if (lane == 31) ws[wid] = sum;
    __syncthreads();
    if (wid == 0) {
        int wsum = ws[lane];
#pragma unroll
        for (int d = 1; d < 32; d <<= 1) {
            int t = __shfl_up_sync(0xffffffffu, wsum, d);
            if (lane >= d) wsum += t;
        }
        ws[lane] = wsum;
    }
    __syncthreads();
    int incl = sum + (wid > 0 ? ws[wid - 1] : 0);
    if (i < len) off[i] = incl - v;
    if (tid == 1023) partial[blk] = incl;
}
__global__ void scanA_kernel() {
    if (blockIdx.x < NBE)
        block_scan_body(g_ecnt, g_eoff, g_pe, EE, blockIdx.x);
    else
        block_scan_body(g_ncnt, g_noff, g_pn, NN, blockIdx.x - NBE);
}

// ---- 3) scanBC: in-block partial-prefix, finalize offsets, re-zero counters ----
__global__ void scanBC_kernel() {
    __shared__ int s_base;
    int b = blockIdx.x;
    bool is_edge = (b < NBE);
    int blk = is_edge ? b : b - NBE;
    const int* part = is_edge ? g_pe : g_pn;

    int tid = threadIdx.x;
    if (tid < 32) {
        int s = 0;
#pragma unroll
        for (int k = 0; k < 4; k++) {
            int idx = tid + k * 32;
            if (idx < blk) s += part[idx];
        }
#pragma unroll
        for (int d = 16; d > 0; d >>= 1)
            s += __shfl_xor_sync(0xffffffffu, s, d);
        if (tid == 0) s_base = s;
    }
    __syncthreads();
    int base = s_base;

    int i = blk * 1024 + tid;
    if (is_edge) {
        if (i < EE) {
            g_eoff[i] += base;
            g_ecnt[i] = 0;            // restore invariant
        }
        if (b == 0 && tid == 0) { g_eoff[EE] = NNZV; g_noff[NN] = NNZV; }
    } else {
        if (i < NN) {
            g_noff[i] += base;
            g_ncnt[i] = 0;            // restore invariant
        }
    }
}

// ---- 4) fill buckets: ATOMIC-FREE (slot = off[bucket] + precomputed rank) ----
__global__ void fill_kernel(const int* __restrict__ rows,
                            const int* __restrict__ cols) {
    int tid = blockIdx.x * blockDim.x + threadIdx.x;
    int stride = gridDim.x * blockDim.x;
    const int4* rows4 = reinterpret_cast<const int4*>(rows);
    const int4* cols4 = reinterpret_cast<const int4*>(cols);
    const int4* erank4 = reinterpret_cast<const int4*>(g_erank);
    const int4* nrank4 = reinterpret_cast<const int4*>(g_nrank);
    for (int u = tid; u < NNZV / 4; u += stride) {
        int4 r = __ldg(rows4 + u);
        int4 c = __ldg(cols4 + u);
        int4 er = erank4[u];
        int4 nr = nrank4[u];
        g_erows[g_eoff[c.x] + er.x] = r.x;
        g_erows[g_eoff[c.y] + er.y] = r.y;
        g_erows[g_eoff[c.z] + er.z] = r.z;
        g_erows[g_eoff[c.w] + er.w] = r.w;
        g_ncols[g_noff[r.x] + nr.x] = c.x;
        g_ncols[g_noff[r.y] + nr.y] = c.y;
        g_ncols[g_noff[r.z] + nr.z] = c.z;
        g_ncols[g_noff[r.w] + nr.w] = c.w;
    }
}

// ---- 5) phase1: m[e] = de^-1 * Σ_{r∈e} Xh[r]  (warp/edge, fp16, MLP=8) ----
__global__ __launch_bounds__(256)
void phase1_kernel() {
    int e = (blockIdx.x * blockDim.x + threadIdx.x) >> 5;
    if (e >= EE) return;
    int lane = threadIdx.x & 31;
    const h4* Xh = reinterpret_cast<const h4*>(g_xh);

    int i = g_eoff[e], end = g_eoff[e + 1];
    float4 acc = make_float4(0.f, 0.f, 0.f, 0.f);
    for (; i + 8 <= end; i += 8) {
        int r[8];
#pragma unroll
        for (int u = 0; u < 8; u++) r[u] = g_erows[i + u];
        h4 v[8];
#pragma unroll
        for (int u = 0; u < 8; u++) v[u] = Xh[r[u] * 32 + lane];
#pragma unroll
        for (int u = 0; u < 8; u++) {
            float2 a = __half22float2(v[u].a), b = __half22float2(v[u].b);
            acc.x += a.x; acc.y += a.y; acc.z += b.x; acc.w += b.y;
        }
    }
    if (i + 4 <= end) {
        int r[4];
#pragma unroll
        for (int u = 0; u < 4; u++) r[u] = g_erows[i + u];
        h4 v[4];
#pragma unroll
        for (int u = 0; u < 4; u++) v[u] = Xh[r[u] * 32 + lane];
#pragma unroll
        for (int u = 0; u < 4; u++) {
            float2 a = __half22float2(v[u].a), b = __half22float2(v[u].b);
            acc.x += a.x; acc.y += a.y; acc.z += b.x; acc.w += b.y;
        }
        i += 4;
    }
    for (; i < end; i++) {
        h4 v = Xh[g_erows[i] * 32 + lane];
        float2 a = __half22float2(v.a), b = __half22float2(v.b);
        acc.x += a.x; acc.y += a.y; acc.z += b.x; acc.w += b.y;
    }
    float d = g_deinv[e];
    acc.x *= d; acc.y *= d; acc.z *= d; acc.w *= d;
    *(reinterpret_cast<float4*>(g_m) + e * (DIM / 4) + lane) = acc;
}

// ---- 6) gemmE: M2h = fp16(m @ W)  BM=32 (625 tiles, fine-grain balance) ----
__global__ __launch_bounds__(256, 2)
void gemmE_kernel(const float* __restrict__ W) {
    extern __shared__ float smem[];
    float* Yt = smem;                 // [DIM][32] k-major: Yt[k*32 + r]
    float* Ws = smem + DIM * 32;      // [DIM][DIM] row-major

    int tid = threadIdx.x;
    int block_row = blockIdx.x * 32;

    for (int i = tid; i < DIM * (DIM / 4); i += 256) {
        int r = i >> 5, c4 = i & 31;
        float4 v = __ldg(reinterpret_cast<const float4*>(W) + r * (DIM / 4) + c4);
        *reinterpret_cast<float4*>(&Ws[r * DIM + c4 * 4]) = v;
    }
    // Stage m tile k-major: 32 rows x 128 dims = 1024 float4 units
    for (int i = tid; i < (DIM / 4) * 32; i += 256) {
        int r = i & 31, c4 = i >> 5;
        int e = block_row + r;
        float4 v = *(reinterpret_cast<const float4*>(g_m) + e * (DIM / 4) + c4);
        Yt[(c4 * 4 + 0) * 32 + r] = v.x;
        Yt[(c4 * 4 + 1) * 32 + r] = v.y;
        Yt[(c4 * 4 + 2) * 32 + r] = v.z;
        Yt[(c4 * 4 + 3) * 32 + r] = v.w;
    }
    __syncthreads();

    int tx = tid & 15;   // 8 output cols: tx*8
    int ty = tid >> 4;   // 2 output rows: ty*2

    float acc[2][8];
#pragma unroll
    for (int i = 0; i < 2; i++)
#pragma unroll
        for (int j = 0; j < 8; j++) acc[i][j] = 0.f;

#pragma unroll 4
    for (int k = 0; k < DIM; k++) {
        float yf[2], wf[8];
        *reinterpret_cast<float2*>(&yf[0]) = *reinterpret_cast<float2*>(&Yt[k * 32 + ty * 2]);
        *reinterpret_cast<float4*>(&wf[0]) = *reinterpret_cast<float4*>(&Ws[k * DIM + tx * 8]);
        *reinterpret_cast<float4*>(&wf[4]) = *reinterpret_cast<float4*>(&Ws[k * DIM + tx * 8 + 4]);
#pragma unroll
        for (int i = 0; i < 2; i++)
#pragma unroll
            for (int j = 0; j < 8; j++)
                acc[i][j] += yf[i] * wf[j];
    }

#pragma unroll
    for (int i = 0; i < 2; i++) {
        int e = block_row + ty * 2 + i;
        alignas(16) __half2 hh[4];
        hh[0] = __floats2half2_rn(acc[i][0], acc[i][1]);
        hh[1] = __floats2half2_rn(acc[i][2], acc[i][3]);
        hh[2] = __floats2half2_rn(acc[i][4], acc[i][5]);
        hh[3] = __floats2half2_rn(acc[i][6], acc[i][7]);
        *reinterpret_cast<uint4*>(&g_m2h[e * DIM + tx * 8]) =
            *reinterpret_cast<uint4*>(hh);
    }
}

// ---- 7) phase2: out[n] = dv^-1/2[n] * Σ_{e∋n} M2h[e]  (warp/node, MLP 8/4) ----
__global__ __launch_bounds__(256)
void phase2_kernel(float* __restrict__ out) {
    int n = (blockIdx.x * blockDim.x + threadIdx.x) >> 5;
    if (n >= NN) return;
    int lane = threadIdx.x & 31;
    const h4* M2 = reinterpret_cast<const h4*>(g_m2h);

    int i = g_noff[n], end = g_noff[n + 1];
    float4 acc = make_float4(0.f, 0.f, 0.f, 0.f);
    for (; i + 8 <= end; i += 8) {
        int c[8];
#pragma unroll
        for (int u = 0; u < 8; u++) c[u] = g_ncols[i + u];
        h4 v[8];
#pragma unroll
        for (int u = 0; u < 8; u++) v[u] = M2[c[u] * 32 + lane];
#pragma unroll
        for (int u = 0; u < 8; u++) {
            float2 a = __half22float2(v[u].a), b = __half22float2(v[u].b);
            acc.x += a.x; acc.y += a.y; acc.z += b.x; acc.w += b.y;
        }
    }
    if (i + 4 <= end) {
        int c[4];
#pragma unroll
        for (int u = 0; u < 4; u++) c[u] = g_ncols[i + u];
        h4 v[4];
#pragma unroll
        for (int u = 0; u < 4; u++) v[u] = M2[c[u] * 32 + lane];
#pragma unroll
        for (int u = 0; u < 4; u++) {
            float2 a = __half22float2(v[u].a), b = __half22float2(v[u].b);
            acc.x += a.x; acc.y += a.y; acc.z += b.x; acc.w += b.y;
        }
        i += 4;
    }
    for (; i < end; i++) {
        h4 v = M2[g_ncols[i] * 32 + lane];
        float2 a = __half22float2(v.a), b = __half22float2(v.b);
        acc.x += a.x; acc.y += a.y; acc.z += b.x; acc.w += b.y;
    }
    float s = g_dvis[n];
    acc.x *= s; acc.y *= s; acc.z *= s; acc.w *= s;
    *(reinterpret_cast<float4*>(out) + n * (DIM / 4) + lane) = acc;
}

extern "C" void kernel_launch(void* const* d_in, const int* in_sizes, int n_in,
                              void* d_out, int out_size) {
    const float* X    = (const float*)d_in[0];
    const int*   rows = (const int*)  d_in[1];
    const int*   cols = (const int*)  d_in[2];
    const float* dv   = (const float*)d_in[3];
    const float* de   = (const float*)d_in[4];
    const float* W    = (const float*)d_in[5];
    float*       out  = (float*)d_out;

    prep_kernel<<<2048, 256>>>(X, dv, de, rows, cols);
    scanA_kernel<<<NBE + NBN, 1024>>>();
    scanBC_kernel<<<NBE + NBN, 1024>>>();
    fill_kernel<<<1024, 256>>>(rows, cols);

    phase1_kernel<<<(EE * 32 + 255) / 256, 256>>>();

    const size_t GEMM_SMEM = (DIM * 32 + DIM * DIM) * sizeof(float);  // 80 KB
    cudaFuncSetAttribute(gemmE_kernel, cudaFuncAttributeMaxDynamicSharedMemorySize,
                         (int)GEMM_SMEM);
    gemmE_kernel<<<EE / 32, 256, GEMM_SMEM>>>(W);

    phase2_kernel<<<((long long)NN * 32 + 255) / 256, 256>>>(out);
}